// round 1
// baseline (speedup 1.0000x reference)
#include <cuda_runtime.h>
#include <cuda_bf16.h>

#define N_NODES 100000
#define N_EDGES 1600000
#define FEATS   64

// ---------------- device scratch (no allocs allowed) ----------------
__device__ int   g_deg[N_NODES];
__device__ int   g_rowptr[N_NODES + 1];
__device__ int   g_cursor[N_NODES];
__device__ int   g_col[N_EDGES];
__device__ float g_hA[N_NODES * FEATS];
__device__ float g_hB[N_NODES * FEATS];
__device__ float g_neigh[N_NODES * FEATS];

// ---------------- CSR build ----------------
__global__ void zero_deg_kernel() {
    int i = blockIdx.x * blockDim.x + threadIdx.x;
    if (i < N_NODES) g_deg[i] = 0;
}

__global__ void hist_kernel(const int* __restrict__ dst) {
    int e = blockIdx.x * blockDim.x + threadIdx.x;
    if (e < N_EDGES) atomicAdd(&g_deg[dst[e]], 1);
}

// single-block exclusive scan of g_deg -> g_rowptr, g_cursor
__global__ void scan_kernel() {
    const int T = 1024;
    const int CH = (N_NODES + T - 1) / T;   // 98
    int tid = threadIdx.x;
    int beg = tid * CH;
    int end = min(N_NODES, beg + CH);

    int s = 0;
    for (int i = beg; i < end; i++) s += g_deg[i];

    __shared__ int sh[T];
    sh[tid] = s;
    __syncthreads();
    // Hillis-Steele inclusive scan
    for (int d = 1; d < T; d <<= 1) {
        int v = (tid >= d) ? sh[tid - d] : 0;
        __syncthreads();
        sh[tid] += v;
        __syncthreads();
    }
    int run = sh[tid] - s;          // exclusive offset for this chunk
    for (int i = beg; i < end; i++) {
        g_rowptr[i] = run;
        g_cursor[i] = run;
        run += g_deg[i];
    }
    if (tid == T - 1) g_rowptr[N_NODES] = sh[T - 1];
}

__global__ void scatter_kernel(const int* __restrict__ src,
                               const int* __restrict__ dst) {
    int e = blockIdx.x * blockDim.x + threadIdx.x;
    if (e < N_EDGES) {
        int pos = atomicAdd(&g_cursor[dst[e]], 1);
        g_col[pos] = src[e];
    }
}

// ---------------- aggregation: one warp per node ----------------
// neigh[n] = mean over in-neighbors of hin[src]
__global__ void agg_kernel(const float* __restrict__ hin) {
    int warp = threadIdx.x >> 5;
    int lane = threadIdx.x & 31;
    int n = blockIdx.x * 8 + warp;          // 12500 blocks * 8 warps = 100000

    int beg = g_rowptr[n];
    int end = g_rowptr[n + 1];
    int cnt = end - beg;

    const float2* hin2 = (const float2*)hin;
    float2 acc = make_float2(0.f, 0.f);

    int e = beg;
    while (e < end) {
        int m = min(8, end - e);
        int c = (lane < m) ? g_col[e + lane] : 0;   // coalesced prefetch
        #pragma unroll
        for (int j = 0; j < 8; j++) {
            if (j < m) {
                int s = __shfl_sync(0xffffffffu, c, j);
                float2 v = hin2[s * 32 + lane];
                acc.x += v.x;
                acc.y += v.y;
            }
        }
        e += m;
    }
    float scale = 1.0f / (float)max(cnt, 1);
    float2* out2 = (float2*)g_neigh;
    out2[n * 32 + lane] = make_float2(acc.x * scale, acc.y * scale);
}

// ---------------- fused dual-GEMV + bias + leaky relu ----------------
// out[n] = hin[n] @ Ws^T + neigh[n] @ Wn^T + b   (optionally leaky-relu)
// block: 256 threads, 32 nodes/block; thread = (node nl = tid>>3, out-group og = tid&7, 8 outs)
template <bool RELU>
__global__ void __launch_bounds__(256) gemm_kernel(const float* __restrict__ hin,
                                                   const float* __restrict__ Ws,
                                                   const float* __restrict__ Wn,
                                                   const float* __restrict__ bias,
                                                   float* __restrict__ out) {
    __shared__ float sWs[64 * 64];
    __shared__ float sWn[64 * 64];
    __shared__ float sh[32 * 64];
    __shared__ float sn[32 * 64];

    int tid = threadIdx.x;
    int node0 = blockIdx.x * 32;

    // load weights (4096 floats each -> 1024 float4 each)
    {
        const float4* w1 = (const float4*)Ws;
        const float4* w2 = (const float4*)Wn;
        float4* d1 = (float4*)sWs;
        float4* d2 = (float4*)sWn;
        #pragma unroll
        for (int i = tid; i < 1024; i += 256) {
            d1[i] = w1[i];
            d2[i] = w2[i];
        }
    }
    // load 32-node tiles (512 float4 each)
    {
        const float4* h4 = (const float4*)(hin + (size_t)node0 * 64);
        const float4* n4 = (const float4*)(g_neigh + (size_t)node0 * 64);
        float4* dh = (float4*)sh;
        float4* dn = (float4*)sn;
        #pragma unroll
        for (int i = tid; i < 512; i += 256) {
            dh[i] = h4[i];
            dn[i] = n4[i];
        }
    }
    __syncthreads();

    int og = tid & 7;            // output group: outs [og*8, og*8+8)
    int nl = tid >> 3;           // local node 0..31
    int obase = og * 8;

    float acc[8];
    #pragma unroll
    for (int o = 0; o < 8; o++) acc[o] = bias[obase + o];

    const float4* hv4 = (const float4*)(sh + nl * 64);
    const float4* nv4 = (const float4*)(sn + nl * 64);

    #pragma unroll
    for (int k4 = 0; k4 < 16; k4++) {
        float4 hv = hv4[k4];
        float4 nv = nv4[k4];
        #pragma unroll
        for (int o = 0; o < 8; o++) {
            float4 w1 = ((const float4*)(sWs + (obase + o) * 64))[k4];
            float4 w2 = ((const float4*)(sWn + (obase + o) * 64))[k4];
            acc[o] += hv.x * w1.x + hv.y * w1.y + hv.z * w1.z + hv.w * w1.w;
            acc[o] += nv.x * w2.x + nv.y * w2.y + nv.z * w2.z + nv.w * w2.w;
        }
    }

    if (RELU) {
        #pragma unroll
        for (int o = 0; o < 8; o++) acc[o] = (acc[o] >= 0.f) ? acc[o] : 0.01f * acc[o];
    }

    float* op = out + (size_t)(node0 + nl) * 64 + obase;
    float4 r0 = make_float4(acc[0], acc[1], acc[2], acc[3]);
    float4 r1 = make_float4(acc[4], acc[5], acc[6], acc[7]);
    ((float4*)op)[0] = r0;
    ((float4*)op)[1] = r1;
}

// ---------------- launch ----------------
extern "C" void kernel_launch(void* const* d_in, const int* in_sizes, int n_in,
                              void* d_out, int out_size) {
    const float* in_feat = (const float*)d_in[0];
    const int*   src     = (const int*)d_in[1];
    const int*   dst     = (const int*)d_in[2];
    const float* w_s1    = (const float*)d_in[3];
    const float* w_n1    = (const float*)d_in[4];
    const float* b1      = (const float*)d_in[5];
    const float* w_s2    = (const float*)d_in[6];
    const float* w_n2    = (const float*)d_in[7];
    const float* b2      = (const float*)d_in[8];
    const float* w_s3    = (const float*)d_in[9];
    const float* w_n3    = (const float*)d_in[10];
    const float* b3      = (const float*)d_in[11];
    float* out = (float*)d_out;

    // resolve device-symbol addresses for passing to kernels
    float* hA;    cudaGetSymbolAddress((void**)&hA, g_hA);
    float* hB;    cudaGetSymbolAddress((void**)&hB, g_hB);

    // --- CSR build (reused by all 3 layers) ---
    zero_deg_kernel<<<(N_NODES + 1023) / 1024, 1024>>>();
    hist_kernel<<<N_EDGES / 256, 256>>>(dst);
    scan_kernel<<<1, 1024>>>();
    scatter_kernel<<<N_EDGES / 256, 256>>>(src, dst);

    // --- layer 1 ---
    agg_kernel<<<N_NODES / 8, 256>>>(in_feat);
    gemm_kernel<true><<<N_NODES / 32, 256>>>(in_feat, w_s1, w_n1, b1, hA);
    // --- layer 2 ---
    agg_kernel<<<N_NODES / 8, 256>>>(hA);
    gemm_kernel<true><<<N_NODES / 32, 256>>>(hA, w_s2, w_n2, b2, hB);
    // --- layer 3 ---
    agg_kernel<<<N_NODES / 8, 256>>>(hB);
    gemm_kernel<false><<<N_NODES / 32, 256>>>(hB, w_s3, w_n3, b3, out);
}

// round 2
// speedup vs baseline: 4.9410x; 4.9410x over previous
#include <cuda_runtime.h>
#include <cuda_bf16.h>

#define N_NODES 100000
#define N_EDGES 1600000
#define FEATS   64
#define PITCH_B 68   // padded pitch for transposed weight tile (floats)

// ---------------- device scratch (no allocs allowed) ----------------
__device__ int   g_deg[N_NODES];
__device__ int   g_rowptr[N_NODES + 1];
__device__ int   g_cursor[N_NODES];
__device__ int   g_col[N_EDGES];
__device__ float g_hA[N_NODES * FEATS];
__device__ float g_hB[N_NODES * FEATS];
__device__ float g_neigh[N_NODES * FEATS];

// ---------------- CSR build ----------------
__global__ void hist_kernel(const int* __restrict__ dst) {
    int e = blockIdx.x * blockDim.x + threadIdx.x;
    if (e < N_EDGES) atomicAdd(&g_deg[dst[e]], 1);
}

// single-block exclusive scan of g_deg -> g_rowptr, g_cursor
__global__ void scan_kernel() {
    const int T = 1024;
    const int CH = (N_NODES + T - 1) / T;   // 98
    int tid = threadIdx.x;
    int beg = tid * CH;
    int end = min(N_NODES, beg + CH);

    int s = 0;
    for (int i = beg; i < end; i++) s += g_deg[i];

    __shared__ int sh[T];
    sh[tid] = s;
    __syncthreads();
    for (int d = 1; d < T; d <<= 1) {
        int v = (tid >= d) ? sh[tid - d] : 0;
        __syncthreads();
        sh[tid] += v;
        __syncthreads();
    }
    int run = sh[tid] - s;
    for (int i = beg; i < end; i++) {
        g_rowptr[i] = run;
        g_cursor[i] = run;
        run += g_deg[i];
    }
    if (tid == T - 1) g_rowptr[N_NODES] = sh[T - 1];
}

__global__ void scatter_kernel(const int* __restrict__ src,
                               const int* __restrict__ dst) {
    int e = blockIdx.x * blockDim.x + threadIdx.x;
    if (e < N_EDGES) {
        int pos = atomicAdd(&g_cursor[dst[e]], 1);
        g_col[pos] = src[e];
    }
}

// ---------------- aggregation: half-warp (16 lanes) per node, float4 lanes ----
__global__ void __launch_bounds__(256) agg_kernel(const float* __restrict__ hin) {
    int tid  = threadIdx.x;
    int warp = tid >> 5;
    int lane = tid & 31;
    int half = lane >> 4;          // 0 or 1
    int hl   = lane & 15;          // lane within half
    int n = blockIdx.x * 16 + warp * 2 + half;   // 6250 blocks * 16 nodes

    unsigned mask = half ? 0xFFFF0000u : 0x0000FFFFu;

    int beg = g_rowptr[n];
    int end = g_rowptr[n + 1];
    int cnt = end - beg;

    const float4* h4 = (const float4*)hin;
    float4 acc = make_float4(0.f, 0.f, 0.f, 0.f);

    for (int e = beg; e < end; e += 16) {
        int m = min(16, end - e);
        int c = (hl < m) ? g_col[e + hl] : 0;
        #pragma unroll
        for (int j = 0; j < 16; j++) {
            if (j < m) {
                int s = __shfl_sync(mask, c, j, 16);
                float4 v = h4[(size_t)s * 16 + hl];
                acc.x += v.x; acc.y += v.y; acc.z += v.z; acc.w += v.w;
            }
        }
    }
    float scale = 1.0f / (float)max(cnt, 1);
    float4 r = make_float4(acc.x * scale, acc.y * scale, acc.z * scale, acc.w * scale);
    ((float4*)g_neigh)[(size_t)n * 16 + hl] = r;
}

// ---------------- register-tiled dual GEMM + bias + leaky relu ----------------
// out[64n x 64o per block] = h_tile @ Ws^T + neigh_tile @ Wn^T + b
// 256 threads: tx = tid%16 -> outs [4tx,4tx+4), ty = tid/16 -> nodes [4ty,4ty+4)
template <bool RELU>
__global__ void __launch_bounds__(256) gemm_kernel(const float* __restrict__ hin,
                                                   const float* __restrict__ Ws,
                                                   const float* __restrict__ Wn,
                                                   const float* __restrict__ bias,
                                                   float* __restrict__ out) {
    __shared__ float A_s[64 * 64];        // [n][k], node-major
    __shared__ float B_s[64 * PITCH_B];   // [k][o], transposed weights, padded

    int tid = threadIdx.x;
    int node0 = blockIdx.x * 64;
    int tx = tid & 15;       // out group
    int ty = tid >> 4;       // node group

    float4 bv = ((const float4*)bias)[tx];
    float acc[4][4];
    #pragma unroll
    for (int j = 0; j < 4; j++) {
        acc[j][0] = bv.x; acc[j][1] = bv.y; acc[j][2] = bv.z; acc[j][3] = bv.w;
    }

    #pragma unroll 1
    for (int chunk = 0; chunk < 2; chunk++) {
        const float* Aptr = (chunk == 0) ? hin : g_neigh;
        const float* Wptr = (chunk == 0) ? Ws  : Wn;

        if (chunk == 1) __syncthreads();   // protect smem reuse

        // --- load A tile: lanes = consecutive feat-chunks (coalesced global) ---
        {
            int c4   = tid & 15;          // float4 column 0..15
            int nrow = tid >> 4;          // node row 0..15, +16 each iter
            #pragma unroll
            for (int i = 0; i < 4; i++) {
                int nr = nrow + i * 16;
                int gn = node0 + nr;
                float4 v = make_float4(0.f, 0.f, 0.f, 0.f);
                if (gn < N_NODES)
                    v = ((const float4*)Aptr)[(size_t)gn * 16 + c4];
                *(float4*)&A_s[nr * 64 + c4 * 4] = v;
            }
        }
        // --- load W transposed into B_s[k][o]: lanes = consecutive o (conflict-free STS) ---
        {
            int o   = tid & 63;           // lanes consecutive o
            int c4w = tid >> 6;           // 0..3, +4 each iter? (covers 16 with 4 iters)
            #pragma unroll
            for (int i = 0; i < 4; i++) {
                int c4 = c4w + i * 4;
                float4 w = ((const float4*)Wptr)[(size_t)o * 16 + c4];
                B_s[(c4 * 4 + 0) * PITCH_B + o] = w.x;
                B_s[(c4 * 4 + 1) * PITCH_B + o] = w.y;
                B_s[(c4 * 4 + 2) * PITCH_B + o] = w.z;
                B_s[(c4 * 4 + 3) * PITCH_B + o] = w.w;
            }
        }
        __syncthreads();

        // --- compute: 4 nodes x 4 outs, K=64 ---
        #pragma unroll
        for (int k4 = 0; k4 < 16; k4++) {
            float4 a[4], b[4];
            #pragma unroll
            for (int j = 0; j < 4; j++)
                a[j] = *(const float4*)&A_s[(4 * ty + j) * 64 + k4 * 4];
            #pragma unroll
            for (int kk = 0; kk < 4; kk++)
                b[kk] = *(const float4*)&B_s[(k4 * 4 + kk) * PITCH_B + 4 * tx];
            #pragma unroll
            for (int j = 0; j < 4; j++) {
                acc[j][0] += a[j].x * b[0].x + a[j].y * b[1].x + a[j].z * b[2].x + a[j].w * b[3].x;
                acc[j][1] += a[j].x * b[0].y + a[j].y * b[1].y + a[j].z * b[2].y + a[j].w * b[3].y;
                acc[j][2] += a[j].x * b[0].z + a[j].y * b[1].z + a[j].z * b[2].z + a[j].w * b[3].z;
                acc[j][3] += a[j].x * b[0].w + a[j].y * b[1].w + a[j].z * b[2].w + a[j].w * b[3].w;
            }
        }
    }

    // --- epilogue ---
    #pragma unroll
    for (int j = 0; j < 4; j++) {
        int gn = node0 + 4 * ty + j;
        if (gn < N_NODES) {
            float4 r;
            r.x = acc[j][0]; r.y = acc[j][1]; r.z = acc[j][2]; r.w = acc[j][3];
            if (RELU) {
                r.x = (r.x >= 0.f) ? r.x : 0.01f * r.x;
                r.y = (r.y >= 0.f) ? r.y : 0.01f * r.y;
                r.z = (r.z >= 0.f) ? r.z : 0.01f * r.z;
                r.w = (r.w >= 0.f) ? r.w : 0.01f * r.w;
            }
            ((float4*)out)[(size_t)gn * 16 + tx] = r;
        }
    }
}

// ---------------- launch ----------------
extern "C" void kernel_launch(void* const* d_in, const int* in_sizes, int n_in,
                              void* d_out, int out_size) {
    const float* in_feat = (const float*)d_in[0];
    const int*   src     = (const int*)d_in[1];
    const int*   dst     = (const int*)d_in[2];
    const float* w_s1    = (const float*)d_in[3];
    const float* w_n1    = (const float*)d_in[4];
    const float* b1      = (const float*)d_in[5];
    const float* w_s2    = (const float*)d_in[6];
    const float* w_n2    = (const float*)d_in[7];
    const float* b2      = (const float*)d_in[8];
    const float* w_s3    = (const float*)d_in[9];
    const float* w_n3    = (const float*)d_in[10];
    const float* b3      = (const float*)d_in[11];
    float* out = (float*)d_out;

    float* hA;  cudaGetSymbolAddress((void**)&hA, g_hA);
    float* hB;  cudaGetSymbolAddress((void**)&hB, g_hB);
    int*   deg; cudaGetSymbolAddress((void**)&deg, g_deg);

    const int GEMM_BLOCKS = (N_NODES + 63) / 64;   // 1563

    // --- CSR build (reused by all 3 layers) ---
    cudaMemsetAsync(deg, 0, N_NODES * sizeof(int));
    hist_kernel<<<N_EDGES / 256, 256>>>(dst);
    scan_kernel<<<1, 1024>>>();
    scatter_kernel<<<N_EDGES / 256, 256>>>(src, dst);

    // --- layer 1 ---
    agg_kernel<<<N_NODES / 16, 256>>>(in_feat);
    gemm_kernel<true><<<GEMM_BLOCKS, 256>>>(in_feat, w_s1, w_n1, b1, hA);
    // --- layer 2 ---
    agg_kernel<<<N_NODES / 16, 256>>>(hA);
    gemm_kernel<true><<<GEMM_BLOCKS, 256>>>(hA, w_s2, w_n2, b2, hB);
    // --- layer 3 ---
    agg_kernel<<<N_NODES / 16, 256>>>(hB);
    gemm_kernel<false><<<GEMM_BLOCKS, 256>>>(hB, w_s3, w_n3, b3, out);
}

// round 3
// speedup vs baseline: 6.4481x; 1.3050x over previous
#include <cuda_runtime.h>
#include <cstdint>

#define N_NODES 100000
#define N_EDGES 1600000
#define FEATS   64
#define PITCH_A 68   // padded pitch for A tile (floats)
#define PITCH_B 68   // padded pitch for transposed weight tile (floats)
#define SCAN_T  1024
#define SCAN_B  ((N_NODES + SCAN_T - 1) / SCAN_T)   // 98

// ---------------- device scratch (no allocs allowed) ----------------
__device__ int   g_deg[N_NODES];
__device__ int   g_rowptr[N_NODES + 1];
__device__ int   g_cursor[N_NODES];
__device__ int   g_col[N_EDGES];
__device__ int   g_bsum[128];
__device__ int   g_boff[128];
__device__ float g_hA[N_NODES * FEATS];
__device__ float g_hB[N_NODES * FEATS];
__device__ float g_neigh[N_NODES * FEATS];

// ---------------- packed f32x2 helpers ----------------
__device__ __forceinline__ void fma2(unsigned long long& d, unsigned long long a,
                                     unsigned long long b) {
    asm("fma.rn.f32x2 %0, %1, %2, %0;" : "+l"(d) : "l"(a), "l"(b));
}
__device__ __forceinline__ void add2(unsigned long long& d, unsigned long long b) {
    asm("add.rn.f32x2 %0, %0, %1;" : "+l"(d) : "l"(b));
}
__device__ __forceinline__ void mul2(unsigned long long& d, unsigned long long b) {
    asm("mul.rn.f32x2 %0, %0, %1;" : "+l"(d) : "l"(b));
}
__device__ __forceinline__ unsigned long long dup2(float x) {
    unsigned long long r;
    unsigned u = __float_as_uint(x);
    asm("mov.b64 %0, {%1, %1};" : "=l"(r) : "r"(u));
    return r;
}
__device__ __forceinline__ void unpack2(unsigned long long v, float& lo, float& hi) {
    unsigned a, b;
    asm("mov.b64 {%0, %1}, %2;" : "=r"(a), "=r"(b) : "l"(v));
    lo = __uint_as_float(a); hi = __uint_as_float(b);
}

// ---------------- CSR build ----------------
__global__ void hist_kernel(const int* __restrict__ dst) {
    int e = blockIdx.x * blockDim.x + threadIdx.x;
    if (e < N_EDGES) atomicAdd(&g_deg[dst[e]], 1);
}

__global__ void block_sum_kernel() {
    __shared__ int sh[SCAN_T];
    int i = blockIdx.x * SCAN_T + threadIdx.x;
    sh[threadIdx.x] = (i < N_NODES) ? g_deg[i] : 0;
    __syncthreads();
    for (int d = SCAN_T / 2; d > 0; d >>= 1) {
        if (threadIdx.x < d) sh[threadIdx.x] += sh[threadIdx.x + d];
        __syncthreads();
    }
    if (threadIdx.x == 0) g_bsum[blockIdx.x] = sh[0];
}

__global__ void scan_small_kernel() {
    __shared__ int sh[128];
    int tid = threadIdx.x;
    int v = (tid < SCAN_B) ? g_bsum[tid] : 0;
    sh[tid] = v;
    __syncthreads();
    for (int d = 1; d < 128; d <<= 1) {
        int t = (tid >= d) ? sh[tid - d] : 0;
        __syncthreads();
        sh[tid] += t;
        __syncthreads();
    }
    if (tid < SCAN_B) g_boff[tid] = sh[tid] - v;      // exclusive
    if (tid == SCAN_B - 1) g_rowptr[N_NODES] = sh[tid];
}

__global__ void fill_rowptr_kernel() {
    __shared__ int sh[SCAN_T];
    int tid = threadIdx.x;
    int i = blockIdx.x * SCAN_T + tid;
    int v = (i < N_NODES) ? g_deg[i] : 0;
    sh[tid] = v;
    __syncthreads();
    for (int d = 1; d < SCAN_T; d <<= 1) {
        int t = (tid >= d) ? sh[tid - d] : 0;
        __syncthreads();
        sh[tid] += t;
        __syncthreads();
    }
    if (i < N_NODES) {
        int ex = g_boff[blockIdx.x] + sh[tid] - v;    // exclusive within-all
        g_rowptr[i] = ex;
        g_cursor[i] = ex;
    }
}

__global__ void scatter_kernel(const int* __restrict__ src,
                               const int* __restrict__ dst) {
    int e = blockIdx.x * blockDim.x + threadIdx.x;
    if (e < N_EDGES) {
        int pos = atomicAdd(&g_cursor[dst[e]], 1);
        g_col[pos] = src[e];
    }
}

// ---------------- aggregation: half-warp per node, packed f32x2 adds ----------
__global__ void __launch_bounds__(256) agg_kernel(const float* __restrict__ hin) {
    int tid  = threadIdx.x;
    int warp = tid >> 5;
    int lane = tid & 31;
    int half = lane >> 4;
    int hl   = lane & 15;
    int n = blockIdx.x * 16 + warp * 2 + half;

    unsigned mask = half ? 0xFFFF0000u : 0x0000FFFFu;

    int beg = g_rowptr[n];
    int end = g_rowptr[n + 1];
    int cnt = end - beg;

    const ulonglong2* h2 = (const ulonglong2*)hin;   // row = 16 ulonglong2
    unsigned long long a0 = 0ull, a1 = 0ull;         // bits of (0.f,0.f)

    for (int e = beg; e < end; e += 16) {
        int m = min(16, end - e);
        int c = (hl < m) ? g_col[e + hl] : 0;
        #pragma unroll
        for (int j = 0; j < 16; j++) {
            if (j < m) {
                int s = __shfl_sync(mask, c, j, 16);
                ulonglong2 v = h2[(size_t)s * 16 + hl];
                add2(a0, v.x);
                add2(a1, v.y);
            }
        }
    }
    unsigned long long s2 = dup2(1.0f / (float)max(cnt, 1));
    mul2(a0, s2);
    mul2(a1, s2);
    ulonglong2 r; r.x = a0; r.y = a1;
    ((ulonglong2*)g_neigh)[(size_t)n * 16 + hl] = r;
}

// ---------------- packed-FFMA2 dual GEMM + bias + leaky relu ------------------
// block tile: 128 nodes x 64 outs, 256 threads, micro-tile 4 nodes x 8 outs
// tx = tid&7 -> outs [8tx, 8tx+8), ty = tid>>3 -> nodes [4ty, 4ty+4)
template <bool RELU>
__global__ void __launch_bounds__(256) gemm_kernel(const float* __restrict__ hin,
                                                   const float* __restrict__ Ws,
                                                   const float* __restrict__ Wn,
                                                   const float* __restrict__ bias,
                                                   float* __restrict__ out) {
    __shared__ float A_s[128 * PITCH_A];   // [n][k] node-major, padded
    __shared__ float B_s[64 * PITCH_B];    // [k][o] transposed weights, padded

    int tid = threadIdx.x;
    int node0 = blockIdx.x * 128;
    int tx = tid & 7;
    int ty = tid >> 3;
    int obase = tx * 8;

    // bias: 4 packed pairs covering outs obase..obase+7
    ulonglong2 bv01 = ((const ulonglong2*)bias)[2 * tx];
    ulonglong2 bv23 = ((const ulonglong2*)bias)[2 * tx + 1];
    unsigned long long acc[4][4];
    #pragma unroll
    for (int j = 0; j < 4; j++) {
        acc[j][0] = bv01.x; acc[j][1] = bv01.y;
        acc[j][2] = bv23.x; acc[j][3] = bv23.y;
    }

    #pragma unroll 1
    for (int chunk = 0; chunk < 2; chunk++) {
        const float* Aptr = (chunk == 0) ? hin : g_neigh;
        const float* Wptr = (chunk == 0) ? Ws  : Wn;

        if (chunk == 1) __syncthreads();

        // --- load A tile: 128 nodes x 16 float4 = 2048 loads over 256 threads ---
        #pragma unroll
        for (int i = 0; i < 8; i++) {
            int idx = tid + i * 256;
            int nr  = idx >> 4;
            int c4  = idx & 15;
            int gn  = node0 + nr;
            float4 v = make_float4(0.f, 0.f, 0.f, 0.f);
            if (gn < N_NODES)
                v = ((const float4*)Aptr)[(size_t)gn * 16 + c4];
            *(float4*)&A_s[nr * PITCH_A + c4 * 4] = v;
        }
        // --- load W transposed into B_s[k][o] (lanes = consecutive o) ---
        {
            int o   = tid & 63;
            int c4w = tid >> 6;
            #pragma unroll
            for (int i = 0; i < 4; i++) {
                int c4 = c4w + i * 4;
                float4 w = ((const float4*)Wptr)[(size_t)o * 16 + c4];
                B_s[(c4 * 4 + 0) * PITCH_B + o] = w.x;
                B_s[(c4 * 4 + 1) * PITCH_B + o] = w.y;
                B_s[(c4 * 4 + 2) * PITCH_B + o] = w.z;
                B_s[(c4 * 4 + 3) * PITCH_B + o] = w.w;
            }
        }
        __syncthreads();

        // --- compute: K=64 in groups of 4 ---
        #pragma unroll 4
        for (int k4 = 0; k4 < 16; k4++) {
            // b packs straight from smem (pairs of adjacent outs)
            unsigned long long b[4][4];
            #pragma unroll
            for (int kk = 0; kk < 4; kk++) {
                const float* row = &B_s[(k4 * 4 + kk) * PITCH_B + obase];
                ulonglong2 b01 = *(const ulonglong2*)row;
                ulonglong2 b23 = *(const ulonglong2*)(row + 4);
                b[kk][0] = b01.x; b[kk][1] = b01.y;
                b[kk][2] = b23.x; b[kk][3] = b23.y;
            }
            #pragma unroll
            for (int j = 0; j < 4; j++) {
                float4 a = *(const float4*)&A_s[(4 * ty + j) * PITCH_A + k4 * 4];
                unsigned long long ad;
                ad = dup2(a.x);
                fma2(acc[j][0], ad, b[0][0]); fma2(acc[j][1], ad, b[0][1]);
                fma2(acc[j][2], ad, b[0][2]); fma2(acc[j][3], ad, b[0][3]);
                ad = dup2(a.y);
                fma2(acc[j][0], ad, b[1][0]); fma2(acc[j][1], ad, b[1][1]);
                fma2(acc[j][2], ad, b[1][2]); fma2(acc[j][3], ad, b[1][3]);
                ad = dup2(a.z);
                fma2(acc[j][0], ad, b[2][0]); fma2(acc[j][1], ad, b[2][1]);
                fma2(acc[j][2], ad, b[2][2]); fma2(acc[j][3], ad, b[2][3]);
                ad = dup2(a.w);
                fma2(acc[j][0], ad, b[3][0]); fma2(acc[j][1], ad, b[3][1]);
                fma2(acc[j][2], ad, b[3][2]); fma2(acc[j][3], ad, b[3][3]);
            }
        }
    }

    // --- epilogue ---
    #pragma unroll
    for (int j = 0; j < 4; j++) {
        int gn = node0 + 4 * ty + j;
        if (gn < N_NODES) {
            float r[8];
            unpack2(acc[j][0], r[0], r[1]);
            unpack2(acc[j][1], r[2], r[3]);
            unpack2(acc[j][2], r[4], r[5]);
            unpack2(acc[j][3], r[6], r[7]);
            if (RELU) {
                #pragma unroll
                for (int o = 0; o < 8; o++) r[o] = (r[o] >= 0.f) ? r[o] : 0.01f * r[o];
            }
            float* op = out + (size_t)gn * 64 + obase;
            ((float4*)op)[0] = make_float4(r[0], r[1], r[2], r[3]);
            ((float4*)op)[1] = make_float4(r[4], r[5], r[6], r[7]);
        }
    }
}

// ---------------- launch ----------------
extern "C" void kernel_launch(void* const* d_in, const int* in_sizes, int n_in,
                              void* d_out, int out_size) {
    const float* in_feat = (const float*)d_in[0];
    const int*   src     = (const int*)d_in[1];
    const int*   dst     = (const int*)d_in[2];
    const float* w_s1    = (const float*)d_in[3];
    const float* w_n1    = (const float*)d_in[4];
    const float* b1      = (const float*)d_in[5];
    const float* w_s2    = (const float*)d_in[6];
    const float* w_n2    = (const float*)d_in[7];
    const float* b2      = (const float*)d_in[8];
    const float* w_s3    = (const float*)d_in[9];
    const float* w_n3    = (const float*)d_in[10];
    const float* b3      = (const float*)d_in[11];
    float* out = (float*)d_out;

    float* hA;  cudaGetSymbolAddress((void**)&hA, g_hA);
    float* hB;  cudaGetSymbolAddress((void**)&hB, g_hB);
    int*   deg; cudaGetSymbolAddress((void**)&deg, g_deg);

    const int GEMM_BLOCKS = (N_NODES + 127) / 128;   // 782

    // --- CSR build (reused by all 3 layers) ---
    cudaMemsetAsync(deg, 0, N_NODES * sizeof(int));
    hist_kernel<<<N_EDGES / 256, 256>>>(dst);
    block_sum_kernel<<<SCAN_B, SCAN_T>>>();
    scan_small_kernel<<<1, 128>>>();
    fill_rowptr_kernel<<<SCAN_B, SCAN_T>>>();
    scatter_kernel<<<N_EDGES / 256, 256>>>(src, dst);

    // --- layer 1 ---
    agg_kernel<<<N_NODES / 16, 256>>>(in_feat);
    gemm_kernel<true><<<GEMM_BLOCKS, 256>>>(in_feat, w_s1, w_n1, b1, hA);
    // --- layer 2 ---
    agg_kernel<<<N_NODES / 16, 256>>>(hA);
    gemm_kernel<true><<<GEMM_BLOCKS, 256>>>(hA, w_s2, w_n2, b2, hB);
    // --- layer 3 ---
    agg_kernel<<<N_NODES / 16, 256>>>(hB);
    gemm_kernel<false><<<GEMM_BLOCKS, 256>>>(hB, w_s3, w_n3, b3, out);
}